// round 13
// baseline (speedup 1.0000x reference)
#include <cuda_runtime.h>
#include <cuda_fp16.h>
#include <cstdint>
#include <cstddef>

#define DM 256
#define NH 8
#define DH 32
#define LQ 4096
#define LK 6144
#define NB 2
#define NKT (LK / 64)

// ---------------- scratch (allocation-free: __device__ globals) ----------------
// Q/K: [b][seq][DM] f16, per-head dh interleaved in 16-groups: slot 4t+{0..3} = dh {2t,2t+1,2t+8,2t+9}
// vT : [b][h][dh][LK] f16, seq interleaved the same way within 16-groups
__device__ __half g_qh[(size_t)NB * LQ * DM];
__device__ __half g_kh[(size_t)NB * LK * DM];
__device__ __half g_vTh[(size_t)NB * NH * DH * LK];

// ---------------- helpers ----------------
__device__ __forceinline__ uint32_t packh2(float a, float b) {
    __half2 h = __floats2half2_rn(a, b);
    return *(uint32_t*)&h;
}

__device__ __forceinline__ uint32_t ex2h2(uint32_t x) {
    uint32_t y;
    asm("ex2.approx.f16x2 %0, %1;" : "=r"(y) : "r"(x));
    return y;
}

__device__ __forceinline__ uint32_t hadd2u(uint32_t a, uint32_t b) {
    __half2 r = __hadd2(*(__half2*)&a, *(__half2*)&b);
    return *(uint32_t*)&r;
}

// f16 m16n8k16, f32 accumulate
__device__ __forceinline__ void mma16(float c[4],
                                      uint32_t a0, uint32_t a1, uint32_t a2, uint32_t a3,
                                      uint32_t b0, uint32_t b1) {
    asm volatile(
        "mma.sync.aligned.m16n8k16.row.col.f32.f16.f16.f32 "
        "{%0,%1,%2,%3},{%4,%5,%6,%7},{%8,%9},{%0,%1,%2,%3};"
        : "+f"(c[0]), "+f"(c[1]), "+f"(c[2]), "+f"(c[3])
        : "r"(a0), "r"(a1), "r"(a2), "r"(a3), "r"(b0), "r"(b1));
}

__device__ __forceinline__ void cp16(uint32_t dst, const void* src) {
    asm volatile("cp.async.ca.shared.global [%0], [%1], 16;" :: "r"(dst), "l"(src));
}
#define CP_COMMIT() asm volatile("cp.async.commit_group;")
#define CP_WAIT(n)  asm volatile("cp.async.wait_group %0;" :: "n"(n))

// =====================================================================
// Projection: C[M, 256] = A[M, 256] @ W^T, f16 mma m16n8k16, f32 accum.
// (unchanged from R12)
// =====================================================================
#define SAH 48

__global__ void __launch_bounds__(256) proj_kernel(const float* __restrict__ A,
                                                   const float* __restrict__ W,
                                                   int which, float scale) {
    __shared__ __align__(16) __half psm[2 * 128 * SAH];   // 24 KB
    __half* sA = psm;
    __half* sB = psm + 128 * SAH;

    const int mt = blockIdx.x, nt = blockIdx.y;
    const int tid = threadIdx.x;
    const int w = tid >> 5, lane = tid & 31, g = lane >> 2, t = lane & 3;

    float acc[16][4];
#pragma unroll
    for (int i = 0; i < 16; i++)
#pragma unroll
        for (int j = 0; j < 4; j++) acc[i][j] = 0.f;

    const float* Ab = A + (size_t)(mt * 128) * DM;
    const float* Wb = W + (size_t)(nt * 128) * DM;

    for (int k0 = 0; k0 < DM; k0 += 32) {
        __syncthreads();
#pragma unroll
        for (int i = 0; i < 4; i++) {
            int fidx = tid + i * 256;
            int row = fidx >> 3, c4 = fidx & 7;
            float4 a = *(const float4*)(Ab + (size_t)row * DM + k0 + c4 * 4);
            int j = c4 & 3, grp = c4 >> 2;
            int s0 = (j < 2) ? 8 * j : 8 * (j - 2) + 2;
            int base = row * SAH + grp * 16 + s0;
            *(uint32_t*)&sA[base]     = packh2(a.x, a.y);
            *(uint32_t*)&sA[base + 4] = packh2(a.z, a.w);
        }
#pragma unroll
        for (int i = 0; i < 4; i++) {
            int fidx = tid + i * 256;
            int row = fidx >> 3, c4 = fidx & 7;
            float4 a = *(const float4*)(Wb + (size_t)row * DM + k0 + c4 * 4);
            int j = c4 & 3, grp = c4 >> 2;
            int s0 = (j < 2) ? 8 * j : 8 * (j - 2) + 2;
            int base = row * SAH + grp * 16 + s0;
            *(uint32_t*)&sB[base]     = packh2(a.x, a.y);
            *(uint32_t*)&sB[base + 4] = packh2(a.z, a.w);
        }
        __syncthreads();

#pragma unroll
        for (int ks = 0; ks < 2; ks++) {
            uint2 lo = *(const uint2*)&sA[(w * 16 + g) * SAH + ks * 16 + t * 4];
            uint2 hi = *(const uint2*)&sA[(w * 16 + g + 8) * SAH + ks * 16 + t * 4];
#pragma unroll
            for (int nf = 0; nf < 16; nf++) {
                uint2 bu = *(const uint2*)&sB[(nf * 8 + g) * SAH + ks * 16 + t * 4];
                mma16(acc[nf], lo.x, hi.x, lo.y, hi.y, bu.x, bu.y);
            }
        }
    }

    if (which != 2) {
        __half* C = (which == 0) ? g_qh : g_kh;
        int row0 = mt * 128 + w * 16 + g;
#pragma unroll
        for (int nf = 0; nf < 16; nf++) {
            int col = nt * 128 + nf * 8 + 2 * t;
            int dh_ = col & 31;
            int grp = dh_ >> 4, jg = dh_ & 15;
            int m = jg >> 1;
            int slot = 4 * (m & 3) + 2 * ((m >> 2) & 1);
            int outcol = (col & ~31) | (grp * 16 + slot);
            *(__half2*)&C[(size_t)row0 * DM + outcol] =
                __floats2half2_rn(acc[nf][0] * scale, acc[nf][1] * scale);
            *(__half2*)&C[(size_t)(row0 + 8) * DM + outcol] =
                __floats2half2_rn(acc[nf][2] * scale, acc[nf][3] * scale);
        }
    } else {
        const int b_ = (mt * 128) / LK;
        const int s0v = mt * 128 - b_ * LK;
        __half* sT = psm;                   // [64][136]
#pragma unroll
        for (int p = 0; p < 2; p++) {
            __syncthreads();
#pragma unroll
            for (int q = 0; q < 8; q++) {
                int nf = p * 8 + q;
                int c = q * 8 + 2 * t;
                int rloc = w * 16 + g;
                sT[c * 136 + rloc]             = __float2half(acc[nf][0]);
                sT[(c + 1) * 136 + rloc]       = __float2half(acc[nf][1]);
                sT[c * 136 + rloc + 8]         = __float2half(acc[nf][2]);
                sT[(c + 1) * 136 + rloc + 8]   = __float2half(acc[nf][3]);
            }
            __syncthreads();
            const int grp16 = lane >> 2, u = lane & 3;
#pragma unroll
            for (int rr = 0; rr < 8; rr++) {
                int row = rr * 8 + w;
                int D = nt * 128 + p * 64 + row;
                int hh = D >> 5, dl = D & 31;
                __half* dst = g_vTh + (((size_t)b_ * NH + hh) * DH + dl) * LK + s0v;
                int sb = grp16 * 16;
                uint2 pk;
                pk.x = *(uint32_t*)&sT[row * 136 + sb + 2 * u];
                pk.y = *(uint32_t*)&sT[row * 136 + sb + 2 * u + 8];
                *(uint2*)&dst[sb + u * 4] = pk;
            }
        }
    }
}

// =====================================================================
// Flash attention, f16 m16n8k16, f32 accumulate. BQ=128, BK=64.
// 128 threads = 4 warps; warp w owns TWO 16-row stripes: rows
// [w*32, w*32+16) and [w*32+16, w*32+32). 4 CTAs/SM -> each SMSP hosts
// warps of 4 independent CTAs with desynchronized softmax/mma phases.
// la row-sums: HADD2 presum of the 4 k-chunk P fragments + ONE ones-mma
// per stripe (66 mma/warp-iter instead of 72).
// smem (halves): sQ [128][48]  sK [2][64][48]  sVT [2][32][80] = 34 KB
// =====================================================================
#define SQH 48
#define SKH 48
#define SVH 80
#define SMEM_H (128 * SQH + 2 * 64 * SKH + 2 * 32 * SVH)
#define ONE2 0x3C003C00u   // half2(1.0, 1.0)

__global__ void __launch_bounds__(128, 4) attn_kernel(float* __restrict__ out) {
    extern __shared__ __half smh[];
    __half* sQ = smh;
    __half* sK = sQ + 128 * SQH;
    __half* sVT = sK + 2 * 64 * SKH;

    const int qt = blockIdx.x;
    const int bh = blockIdx.y;
    const int b = bh >> 3, h = bh & 7;
    const int tid = threadIdx.x;
    const int w = tid >> 5, lane = tid & 31, g = lane >> 2, t = lane & 3;

    const __half* qb = g_qh + ((size_t)b * LQ) * DM + h * DH;
    const __half* kb = g_kh + ((size_t)b * LK) * DM + h * DH;
    const __half* vtb = g_vTh + (((size_t)b * NH + h) * DH) * LK;

    const uint32_t sQa = (uint32_t)__cvta_generic_to_shared(sQ);
    const uint32_t sKa = (uint32_t)__cvta_generic_to_shared(sK);
    const uint32_t sVa = (uint32_t)__cvta_generic_to_shared(sVT);

    // ---- prologue: Q tile [128][32]h + K/V stage 0 ----
    {
        int q0 = qt * 128;
#pragma unroll
        for (int i = 0; i < 4; i++) {
            int fidx = tid + i * 128;          // 0..511
            int row = fidx >> 2, c4 = fidx & 3;
            cp16(sQa + (uint32_t)(row * SQH + c4 * 8) * 2,
                 qb + (size_t)(q0 + row) * DM + c4 * 8);
        }
#pragma unroll
        for (int i = 0; i < 4; i++) {
            int fidx = tid + i * 128;          // 0..511
            if (fidx < 256) {
                int row = fidx >> 2, c = fidx & 3;
                cp16(sKa + (uint32_t)(row * SKH + c * 8) * 2,
                     kb + (size_t)row * DM + c * 8);
            } else {
                int f = fidx - 256;
                int d = f >> 3, c = f & 7;
                cp16(sVa + (uint32_t)(d * SVH + c * 8) * 2,
                     vtb + (size_t)d * LK + c * 8);
            }
        }
        CP_COMMIT();
    }
    CP_WAIT(0);
    __syncthreads();

    // ---- hoist Q fragments for both stripes ----
    uint32_t qa[2][2][4];
#pragma unroll
    for (int st = 0; st < 2; st++) {
#pragma unroll
        for (int ks = 0; ks < 2; ks++) {
            uint2 lo = *(const uint2*)&sQ[(w * 32 + st * 16 + g) * SQH + ks * 16 + t * 4];
            uint2 hi = *(const uint2*)&sQ[(w * 32 + st * 16 + g + 8) * SQH + ks * 16 + t * 4];
            qa[st][ks][0] = lo.x;
            qa[st][ks][2] = lo.y;
            qa[st][ks][1] = hi.x;
            qa[st][ks][3] = hi.y;
        }
    }

    float la[2][4];
    float o[2][4][4];
#pragma unroll
    for (int st = 0; st < 2; st++) {
#pragma unroll
        for (int j = 0; j < 4; j++) la[st][j] = 0.f;
#pragma unroll
        for (int i = 0; i < 4; i++)
#pragma unroll
            for (int j = 0; j < 4; j++) o[st][i][j] = 0.f;
    }

    for (int kt = 0; kt < NKT; kt++) {
        const int buf = kt & 1;

        // ---- prefetch next K/V stage ----
        if (kt + 1 < NKT) {
            int k0 = (kt + 1) * 64;
            uint32_t dK = sKa + (uint32_t)(((kt + 1) & 1) * 64 * SKH) * 2;
            uint32_t dV = sVa + (uint32_t)(((kt + 1) & 1) * 32 * SVH) * 2;
#pragma unroll
            for (int i = 0; i < 4; i++) {
                int fidx = tid + i * 128;
                if (fidx < 256) {
                    int row = fidx >> 2, c = fidx & 3;
                    cp16(dK + (uint32_t)(row * SKH + c * 8) * 2,
                         kb + (size_t)(k0 + row) * DM + c * 8);
                } else {
                    int f = fidx - 256;
                    int d = f >> 3, c = f & 7;
                    cp16(dV + (uint32_t)(d * SVH + c * 8) * 2,
                         vtb + (size_t)d * LK + k0 + c * 8);
                }
            }
            CP_COMMIT();
            CP_WAIT(1);
        } else {
            CP_WAIT(0);
        }
        __syncthreads();

        const __half* cK = sK + buf * 64 * SKH;
        const __half* cV = sVT + buf * 32 * SVH;

        // ---- S + softmax per stripe; la presum via HADD2 + one mma ----
        uint32_t ph[2][8][2];
#pragma unroll
        for (int st = 0; st < 2; st++) {
            float s[8][4];
#pragma unroll
            for (int i = 0; i < 8; i++)
#pragma unroll
                for (int j = 0; j < 4; j++) s[i][j] = 0.f;

#pragma unroll
            for (int ks = 0; ks < 2; ks++) {
#pragma unroll
                for (int nf = 0; nf < 8; nf++) {
                    uint2 bu = *(const uint2*)&cK[(nf * 8 + g) * SKH + ks * 16 + t * 4];
                    mma16(s[nf], qa[st][ks][0], qa[st][ks][1],
                          qa[st][ks][2], qa[st][ks][3], bu.x, bu.y);
                }
            }
#pragma unroll
            for (int nf = 0; nf < 8; nf++) {
                ph[st][nf][0] = ex2h2(packh2(s[nf][0], s[nf][1]));
                ph[st][nf][1] = ex2h2(packh2(s[nf][2], s[nf][3]));
            }
            // presum the 4 even-nf and 4 odd-nf fragments (linearity of mma in A)
            uint32_t a0 = hadd2u(hadd2u(ph[st][0][0], ph[st][2][0]),
                                 hadd2u(ph[st][4][0], ph[st][6][0]));
            uint32_t a1 = hadd2u(hadd2u(ph[st][0][1], ph[st][2][1]),
                                 hadd2u(ph[st][4][1], ph[st][6][1]));
            uint32_t a2 = hadd2u(hadd2u(ph[st][1][0], ph[st][3][0]),
                                 hadd2u(ph[st][5][0], ph[st][7][0]));
            uint32_t a3 = hadd2u(hadd2u(ph[st][1][1], ph[st][3][1]),
                                 hadd2u(ph[st][5][1], ph[st][7][1]));
            mma16(la[st], a0, a1, a2, a3, ONE2, ONE2);   // row sums
        }

        // ---- PV: each V fragment loaded once, feeds both stripes ----
#pragma unroll
        for (int ks = 0; ks < 4; ks++) {
#pragma unroll
            for (int nf2 = 0; nf2 < 4; nf2++) {
                uint2 vv = *(const uint2*)&cV[(nf2 * 8 + g) * SVH + ks * 16 + t * 4];
                mma16(o[0][nf2], ph[0][2 * ks][0], ph[0][2 * ks][1],
                      ph[0][2 * ks + 1][0], ph[0][2 * ks + 1][1], vv.x, vv.y);
                mma16(o[1][nf2], ph[1][2 * ks][0], ph[1][2 * ks][1],
                      ph[1][2 * ks + 1][0], ph[1][2 * ks + 1][1], vv.x, vv.y);
            }
        }

        __syncthreads();   // release buf for the prefetch two iterations ahead
    }

    // ---- epilogue: every lane holds full row sums in la[st][0]/la[st][2] ----
    float* ob = out + ((size_t)b * LQ) * DM + h * DH;
#pragma unroll
    for (int st = 0; st < 2; st++) {
        float inv0 = 1.f / la[st][0], inv1 = 1.f / la[st][2];
        int row0 = qt * 128 + w * 32 + st * 16 + g;
#pragma unroll
        for (int nf = 0; nf < 4; nf++) {
            int c = nf * 8 + 2 * t;
            ob[(size_t)row0 * DM + c]           = o[st][nf][0] * inv0;
            ob[(size_t)row0 * DM + c + 1]       = o[st][nf][1] * inv0;
            ob[(size_t)(row0 + 8) * DM + c]     = o[st][nf][2] * inv1;
            ob[(size_t)(row0 + 8) * DM + c + 1] = o[st][nf][3] * inv1;
        }
    }
}

// =====================================================================
// launcher
// =====================================================================
extern "C" void kernel_launch(void* const* d_in, const int* in_sizes, int n_in,
                              void* d_out, int out_size) {
    (void)in_sizes; (void)n_in; (void)out_size;
    const float* x   = (const float*)d_in[0];
    const float* src = (const float*)d_in[1];
    const float* Wq  = (const float*)d_in[2];
    const float* Wk  = (const float*)d_in[3];
    const float* Wv  = (const float*)d_in[4];
    float* out = (float*)d_out;

    // DH^-0.5 * log2(e): softmax runs in exp2 domain
    const float scale = 0.17677669529663689f * 1.4426950408889634f;

    proj_kernel<<<dim3(NB * LQ / 128, 2), 256>>>(x,   Wq, 0, scale);
    proj_kernel<<<dim3(NB * LK / 128, 2), 256>>>(src, Wk, 1, 1.0f);
    proj_kernel<<<dim3(NB * LK / 128, 2), 256>>>(src, Wv, 2, 1.0f);

    const int smem_bytes = SMEM_H * 2;   // 34816 B
    cudaFuncSetAttribute(attn_kernel, cudaFuncAttributeMaxDynamicSharedMemorySize,
                         smem_bytes);
    attn_kernel<<<dim3(LQ / 128, NB * NH), 128, smem_bytes>>>(out);
}

// round 16
// speedup vs baseline: 1.0577x; 1.0577x over previous
#include <cuda_runtime.h>
#include <cuda_fp16.h>
#include <cstdint>
#include <cstddef>

#define DM 256
#define NH 8
#define DH 32
#define LQ 4096
#define LK 6144
#define NB 2
#define NKT (LK / 64)

// ---------------- scratch (allocation-free: __device__ globals) ----------------
// Q/K: [b][seq][DM] f16, per-head dh interleaved in 16-groups: slot 4t+{0..3} = dh {2t,2t+1,2t+8,2t+9}
// vT : [b][h][dh][LK] f16, seq interleaved the same way within 16-groups
__device__ __half g_qh[(size_t)NB * LQ * DM];
__device__ __half g_kh[(size_t)NB * LK * DM];
__device__ __half g_vTh[(size_t)NB * NH * DH * LK];

// ---------------- helpers ----------------
__device__ __forceinline__ uint32_t packh2(float a, float b) {
    __half2 h = __floats2half2_rn(a, b);
    return *(uint32_t*)&h;
}

__device__ __forceinline__ uint32_t ex2h2(uint32_t x) {
    uint32_t y;
    asm("ex2.approx.f16x2 %0, %1;" : "=r"(y) : "r"(x));
    return y;
}

__device__ __forceinline__ uint32_t hadd2u(uint32_t a, uint32_t b) {
    __half2 r = __hadd2(*(__half2*)&a, *(__half2*)&b);
    return *(uint32_t*)&r;
}

// f16 m16n8k16, f32 accumulate
__device__ __forceinline__ void mma16(float c[4],
                                      uint32_t a0, uint32_t a1, uint32_t a2, uint32_t a3,
                                      uint32_t b0, uint32_t b1) {
    asm volatile(
        "mma.sync.aligned.m16n8k16.row.col.f32.f16.f16.f32 "
        "{%0,%1,%2,%3},{%4,%5,%6,%7},{%8,%9},{%0,%1,%2,%3};"
        : "+f"(c[0]), "+f"(c[1]), "+f"(c[2]), "+f"(c[3])
        : "r"(a0), "r"(a1), "r"(a2), "r"(a3), "r"(b0), "r"(b1));
}

__device__ __forceinline__ void cp16(uint32_t dst, const void* src) {
    asm volatile("cp.async.ca.shared.global [%0], [%1], 16;" :: "r"(dst), "l"(src));
}
#define CP_COMMIT() asm volatile("cp.async.commit_group;")
#define CP_WAIT(n)  asm volatile("cp.async.wait_group %0;" :: "n"(n))

// =====================================================================
// Projection: C[M, 256] = A[M, 256] @ W^T, f16 mma m16n8k16, f32 accum.
// BM=128, BN=128, BK=32. 256 threads = 8 warps.
// (byte-identical to the R12 kernel that passed)
// =====================================================================
#define SAH 48

__global__ void __launch_bounds__(256) proj_kernel(const float* __restrict__ A,
                                                   const float* __restrict__ W,
                                                   int which, float scale) {
    __shared__ __align__(16) __half psm[2 * 128 * SAH];   // 24 KB
    __half* sA = psm;
    __half* sB = psm + 128 * SAH;

    const int mt = blockIdx.x, nt = blockIdx.y;
    const int tid = threadIdx.x;
    const int w = tid >> 5, lane = tid & 31, g = lane >> 2, t = lane & 3;

    float acc[16][4];
#pragma unroll
    for (int i = 0; i < 16; i++)
#pragma unroll
        for (int j = 0; j < 4; j++) acc[i][j] = 0.f;

    const float* Ab = A + (size_t)(mt * 128) * DM;
    const float* Wb = W + (size_t)(nt * 128) * DM;

    for (int k0 = 0; k0 < DM; k0 += 32) {
        __syncthreads();
#pragma unroll
        for (int i = 0; i < 4; i++) {
            int fidx = tid + i * 256;
            int row = fidx >> 3, c4 = fidx & 7;
            float4 a = *(const float4*)(Ab + (size_t)row * DM + k0 + c4 * 4);
            int j = c4 & 3, grp = c4 >> 2;
            int s0 = (j < 2) ? 8 * j : 8 * (j - 2) + 2;
            int base = row * SAH + grp * 16 + s0;
            *(uint32_t*)&sA[base]     = packh2(a.x, a.y);
            *(uint32_t*)&sA[base + 4] = packh2(a.z, a.w);
        }
#pragma unroll
        for (int i = 0; i < 4; i++) {
            int fidx = tid + i * 256;
            int row = fidx >> 3, c4 = fidx & 7;
            float4 a = *(const float4*)(Wb + (size_t)row * DM + k0 + c4 * 4);
            int j = c4 & 3, grp = c4 >> 2;
            int s0 = (j < 2) ? 8 * j : 8 * (j - 2) + 2;
            int base = row * SAH + grp * 16 + s0;
            *(uint32_t*)&sB[base]     = packh2(a.x, a.y);
            *(uint32_t*)&sB[base + 4] = packh2(a.z, a.w);
        }
        __syncthreads();

#pragma unroll
        for (int ks = 0; ks < 2; ks++) {
            uint2 lo = *(const uint2*)&sA[(w * 16 + g) * SAH + ks * 16 + t * 4];
            uint2 hi = *(const uint2*)&sA[(w * 16 + g + 8) * SAH + ks * 16 + t * 4];
#pragma unroll
            for (int nf = 0; nf < 16; nf++) {
                uint2 bu = *(const uint2*)&sB[(nf * 8 + g) * SAH + ks * 16 + t * 4];
                mma16(acc[nf], lo.x, hi.x, lo.y, hi.y, bu.x, bu.y);
            }
        }
    }

    if (which != 2) {
        __half* C = (which == 0) ? g_qh : g_kh;
        int row0 = mt * 128 + w * 16 + g;
#pragma unroll
        for (int nf = 0; nf < 16; nf++) {
            int col = nt * 128 + nf * 8 + 2 * t;
            int dh_ = col & 31;
            int grp = dh_ >> 4, jg = dh_ & 15;
            int m = jg >> 1;
            int slot = 4 * (m & 3) + 2 * ((m >> 2) & 1);
            int outcol = (col & ~31) | (grp * 16 + slot);
            *(__half2*)&C[(size_t)row0 * DM + outcol] =
                __floats2half2_rn(acc[nf][0] * scale, acc[nf][1] * scale);
            *(__half2*)&C[(size_t)(row0 + 8) * DM + outcol] =
                __floats2half2_rn(acc[nf][2] * scale, acc[nf][3] * scale);
        }
    } else {
        const int b_ = (mt * 128) / LK;
        const int s0v = mt * 128 - b_ * LK;
        __half* sT = psm;                   // [64][136]
#pragma unroll
        for (int p = 0; p < 2; p++) {
            __syncthreads();
#pragma unroll
            for (int q = 0; q < 8; q++) {
                int nf = p * 8 + q;
                int c = q * 8 + 2 * t;
                int rloc = w * 16 + g;
                sT[c * 136 + rloc]             = __float2half(acc[nf][0]);
                sT[(c + 1) * 136 + rloc]       = __float2half(acc[nf][1]);
                sT[c * 136 + rloc + 8]         = __float2half(acc[nf][2]);
                sT[(c + 1) * 136 + rloc + 8]   = __float2half(acc[nf][3]);
            }
            __syncthreads();
            const int grp16 = lane >> 2, u = lane & 3;
#pragma unroll
            for (int rr = 0; rr < 8; rr++) {
                int row = rr * 8 + w;
                int D = nt * 128 + p * 64 + row;
                int hh = D >> 5, dl = D & 31;
                __half* dst = g_vTh + (((size_t)b_ * NH + hh) * DH + dl) * LK + s0v;
                int sb = grp16 * 16;
                uint2 pk;
                pk.x = *(uint32_t*)&sT[row * 136 + sb + 2 * u];
                pk.y = *(uint32_t*)&sT[row * 136 + sb + 2 * u + 8];
                *(uint2*)&dst[sb + u * 4] = pk;
            }
        }
    }
}

// =====================================================================
// Flash attention, f16 m16n8k16, f32 accumulate. BQ=256, BK=64.
// 256 threads = 8 warps; warp w owns TWO 16-row stripes (rows w*32..w*32+31).
// V fragments + cp.async tiles shared across stripes. P never touches smem;
// softmax in f16x2. la row-sums: HADD2 presum of the 4 k-chunk P fragments
// + ONE ones-mma per stripe (66 mma/warp-iter instead of 72).
// Otherwise byte-identical to the R12 kernel that passed at 140.4 us.
// smem (halves): sQ [256][48]  sK [2][64][48]  sVT [2][32][80] = 46 KB
// =====================================================================
#define SQH 48
#define SKH 48
#define SVH 80
#define SMEM_H (256 * SQH + 2 * 64 * SKH + 2 * 32 * SVH)
#define ONE2 0x3C003C00u   // half2(1.0, 1.0)

__global__ void __launch_bounds__(256, 2) attn_kernel(float* __restrict__ out) {
    extern __shared__ __half smh[];
    __half* sQ = smh;
    __half* sK = sQ + 256 * SQH;
    __half* sVT = sK + 2 * 64 * SKH;

    const int qt = blockIdx.x;
    const int bh = blockIdx.y;
    const int b = bh >> 3, h = bh & 7;
    const int tid = threadIdx.x;
    const int w = tid >> 5, lane = tid & 31, g = lane >> 2, t = lane & 3;

    const __half* qb = g_qh + ((size_t)b * LQ) * DM + h * DH;
    const __half* kb = g_kh + ((size_t)b * LK) * DM + h * DH;
    const __half* vtb = g_vTh + (((size_t)b * NH + h) * DH) * LK;

    const uint32_t sQa = (uint32_t)__cvta_generic_to_shared(sQ);
    const uint32_t sKa = (uint32_t)__cvta_generic_to_shared(sK);
    const uint32_t sVa = (uint32_t)__cvta_generic_to_shared(sVT);

    // ---- prologue: Q tile [256][32]h + K/V stage 0 ----
    {
        int q0 = qt * 256;
#pragma unroll
        for (int i = 0; i < 4; i++) {
            int fidx = tid + i * 256;          // 0..1023
            int row = fidx >> 2, c4 = fidx & 3;
            cp16(sQa + (uint32_t)(row * SQH + c4 * 8) * 2,
                 qb + (size_t)(q0 + row) * DM + c4 * 8);
        }
#pragma unroll
        for (int i = 0; i < 2; i++) {
            int fidx = tid + i * 256;
            if (fidx < 256) {
                int row = fidx >> 2, c = fidx & 3;
                cp16(sKa + (uint32_t)(row * SKH + c * 8) * 2,
                     kb + (size_t)row * DM + c * 8);
            } else {
                int f = fidx - 256;
                int d = f >> 3, c = f & 7;
                cp16(sVa + (uint32_t)(d * SVH + c * 8) * 2,
                     vtb + (size_t)d * LK + c * 8);
            }
        }
        CP_COMMIT();
    }
    CP_WAIT(0);
    __syncthreads();

    // ---- hoist Q fragments for both stripes ----
    uint32_t qa[2][2][4];
#pragma unroll
    for (int st = 0; st < 2; st++) {
#pragma unroll
        for (int ks = 0; ks < 2; ks++) {
            uint2 lo = *(const uint2*)&sQ[(w * 32 + st * 16 + g) * SQH + ks * 16 + t * 4];
            uint2 hi = *(const uint2*)&sQ[(w * 32 + st * 16 + g + 8) * SQH + ks * 16 + t * 4];
            qa[st][ks][0] = lo.x;
            qa[st][ks][2] = lo.y;
            qa[st][ks][1] = hi.x;
            qa[st][ks][3] = hi.y;
        }
    }

    float la[2][4];
    float o[2][4][4];
#pragma unroll
    for (int st = 0; st < 2; st++) {
#pragma unroll
        for (int j = 0; j < 4; j++) la[st][j] = 0.f;
#pragma unroll
        for (int i = 0; i < 4; i++)
#pragma unroll
            for (int j = 0; j < 4; j++) o[st][i][j] = 0.f;
    }

    for (int kt = 0; kt < NKT; kt++) {
        const int buf = kt & 1;

        // ---- prefetch next K/V stage ----
        if (kt + 1 < NKT) {
            int k0 = (kt + 1) * 64;
            uint32_t dK = sKa + (uint32_t)(((kt + 1) & 1) * 64 * SKH) * 2;
            uint32_t dV = sVa + (uint32_t)(((kt + 1) & 1) * 32 * SVH) * 2;
#pragma unroll
            for (int i = 0; i < 2; i++) {
                int fidx = tid + i * 256;
                if (fidx < 256) {
                    int row = fidx >> 2, c = fidx & 3;
                    cp16(dK + (uint32_t)(row * SKH + c * 8) * 2,
                         kb + (size_t)(k0 + row) * DM + c * 8);
                } else {
                    int f = fidx - 256;
                    int d = f >> 3, c = f & 7;
                    cp16(dV + (uint32_t)(d * SVH + c * 8) * 2,
                         vtb + (size_t)d * LK + k0 + c * 8);
                }
            }
            CP_COMMIT();
            CP_WAIT(1);
        } else {
            CP_WAIT(0);
        }
        __syncthreads();

        const __half* cK = sK + buf * 64 * SKH;
        const __half* cV = sVT + buf * 32 * SVH;

        // ---- S + softmax per stripe; la presum via HADD2 + one mma ----
        uint32_t ph[2][8][2];
#pragma unroll
        for (int st = 0; st < 2; st++) {
            float s[8][4];
#pragma unroll
            for (int i = 0; i < 8; i++)
#pragma unroll
                for (int j = 0; j < 4; j++) s[i][j] = 0.f;

#pragma unroll
            for (int ks = 0; ks < 2; ks++) {
#pragma unroll
                for (int nf = 0; nf < 8; nf++) {
                    uint2 bu = *(const uint2*)&cK[(nf * 8 + g) * SKH + ks * 16 + t * 4];
                    mma16(s[nf], qa[st][ks][0], qa[st][ks][1],
                          qa[st][ks][2], qa[st][ks][3], bu.x, bu.y);
                }
            }
#pragma unroll
            for (int nf = 0; nf < 8; nf++) {
                ph[st][nf][0] = ex2h2(packh2(s[nf][0], s[nf][1]));
                ph[st][nf][1] = ex2h2(packh2(s[nf][2], s[nf][3]));
            }
            // presum the 4 even-nf and 4 odd-nf fragments (linearity of mma in A)
            uint32_t a0 = hadd2u(hadd2u(ph[st][0][0], ph[st][2][0]),
                                 hadd2u(ph[st][4][0], ph[st][6][0]));
            uint32_t a1 = hadd2u(hadd2u(ph[st][0][1], ph[st][2][1]),
                                 hadd2u(ph[st][4][1], ph[st][6][1]));
            uint32_t a2 = hadd2u(hadd2u(ph[st][1][0], ph[st][3][0]),
                                 hadd2u(ph[st][5][0], ph[st][7][0]));
            uint32_t a3 = hadd2u(hadd2u(ph[st][1][1], ph[st][3][1]),
                                 hadd2u(ph[st][5][1], ph[st][7][1]));
            mma16(la[st], a0, a1, a2, a3, ONE2, ONE2);   // row sums
        }

        // ---- PV: each V fragment loaded once, feeds both stripes ----
#pragma unroll
        for (int ks = 0; ks < 4; ks++) {
#pragma unroll
            for (int nf2 = 0; nf2 < 4; nf2++) {
                uint2 vv = *(const uint2*)&cV[(nf2 * 8 + g) * SVH + ks * 16 + t * 4];
                mma16(o[0][nf2], ph[0][2 * ks][0], ph[0][2 * ks][1],
                      ph[0][2 * ks + 1][0], ph[0][2 * ks + 1][1], vv.x, vv.y);
                mma16(o[1][nf2], ph[1][2 * ks][0], ph[1][2 * ks][1],
                      ph[1][2 * ks + 1][0], ph[1][2 * ks + 1][1], vv.x, vv.y);
            }
        }

        __syncthreads();   // release buf for the prefetch two iterations ahead
    }

    // ---- epilogue: every lane holds full row sums in la[st][0]/la[st][2] ----
    float* ob = out + ((size_t)b * LQ) * DM + h * DH;
#pragma unroll
    for (int st = 0; st < 2; st++) {
        float inv0 = 1.f / la[st][0], inv1 = 1.f / la[st][2];
        int row0 = qt * 256 + w * 32 + st * 16 + g;
#pragma unroll
        for (int nf = 0; nf < 4; nf++) {
            int c = nf * 8 + 2 * t;
            ob[(size_t)row0 * DM + c]           = o[st][nf][0] * inv0;
            ob[(size_t)row0 * DM + c + 1]       = o[st][nf][1] * inv0;
            ob[(size_t)(row0 + 8) * DM + c]     = o[st][nf][2] * inv1;
            ob[(size_t)(row0 + 8) * DM + c + 1] = o[st][nf][3] * inv1;
        }
    }
}

// =====================================================================
// launcher (R12-proven three-launch projection)
// =====================================================================
extern "C" void kernel_launch(void* const* d_in, const int* in_sizes, int n_in,
                              void* d_out, int out_size) {
    (void)in_sizes; (void)n_in; (void)out_size;
    const float* x   = (const float*)d_in[0];
    const float* src = (const float*)d_in[1];
    const float* Wq  = (const float*)d_in[2];
    const float* Wk  = (const float*)d_in[3];
    const float* Wv  = (const float*)d_in[4];
    float* out = (float*)d_out;

    // DH^-0.5 * log2(e): softmax runs in exp2 domain
    const float scale = 0.17677669529663689f * 1.4426950408889634f;

    proj_kernel<<<dim3(NB * LQ / 128, 2), 256>>>(x,   Wq, 0, scale);
    proj_kernel<<<dim3(NB * LK / 128, 2), 256>>>(src, Wk, 1, 1.0f);
    proj_kernel<<<dim3(NB * LK / 128, 2), 256>>>(src, Wv, 2, 1.0f);

    const int smem_bytes = SMEM_H * 2;   // 47104 B
    cudaFuncSetAttribute(attn_kernel, cudaFuncAttributeMaxDynamicSharedMemorySize,
                         smem_bytes);
    attn_kernel<<<dim3(LQ / 256, NB * NH), 256, smem_bytes>>>(out);
}